// round 3
// baseline (speedup 1.0000x reference)
#include <cuda_runtime.h>
#include <math.h>

// Shapes
#define BB 128
#define SS 768
#define CC 384
#define MM (BB*SS)      // 98304 tokens

// ---------------- scratch (device globals; no runtime alloc) ----------------
// Aliased layout (~1.06 GB total):
//   g_t0  : tokens channels-last; reused as t3 (pre-LN2) after attention phase
//   g_t1  : residual accumulator / final LN output
//   g_t2  : post-LN1 tokens
//   g_big : attention phase -> qkv at col 0 (1152 cols), ao at +MM*1152 (384 cols)
//           mlp phase       -> mlp hidden (1536 cols)
__device__ float g_t0[(size_t)MM * CC];
__device__ float g_t1[(size_t)MM * CC];
__device__ float g_t2[(size_t)MM * CC];
__device__ float g_big[(size_t)MM * 1536];

// ---------------- transposes ----------------
// x (B, C, S) -> t0 (B*S, C)
__global__ void transpose_in_kernel(const float* __restrict__ x, float* __restrict__ t0) {
    __shared__ float tile[32][33];
    int b = blockIdx.z;
    int s0 = blockIdx.x * 32;
    int c0 = blockIdx.y * 32;
    int tx = threadIdx.x, ty = threadIdx.y;  // (32,8)
    const float* xp = x + (size_t)b * CC * SS;
#pragma unroll
    for (int yy = 0; yy < 32; yy += 8)
        tile[ty + yy][tx] = xp[(size_t)(c0 + ty + yy) * SS + s0 + tx];
    __syncthreads();
    float* tp = t0 + (size_t)b * SS * CC;
#pragma unroll
    for (int yy = 0; yy < 32; yy += 8)
        tp[(size_t)(s0 + ty + yy) * CC + c0 + tx] = tile[tx][ty + yy];
}

// t (B*S, C) -> out (B, C, S)
__global__ void transpose_out_kernel(const float* __restrict__ t, float* __restrict__ out) {
    __shared__ float tile[32][33];
    int b = blockIdx.z;
    int s0 = blockIdx.x * 32;
    int c0 = blockIdx.y * 32;
    int tx = threadIdx.x, ty = threadIdx.y;
    const float* tp = t + (size_t)b * SS * CC;
#pragma unroll
    for (int yy = 0; yy < 32; yy += 8)
        tile[ty + yy][tx] = tp[(size_t)(s0 + ty + yy) * CC + c0 + tx];
    __syncthreads();
    float* op = out + (size_t)b * CC * SS;
#pragma unroll
    for (int yy = 0; yy < 32; yy += 8)
        op[(size_t)(c0 + ty + yy) * SS + s0 + tx] = tile[tx][ty + yy];
}

// ---------------- SGEMM: C[M,N] (op)= A[M,K] * W[K,N], fused epilogues ----------------
// 128x128 tile, 8-deep K slices, double-buffered smem (global->reg prefetch).
enum { EPI_STORE = 0, EPI_ACCUM_BIAS = 1, EPI_GELU_BIAS = 2, EPI_BIAS_RESID = 3 };

template <int MODE>
__global__ __launch_bounds__(256) void sgemm_kernel(
    const float* __restrict__ A, const float* __restrict__ W,
    float* __restrict__ C, const float* __restrict__ bias,
    const float* __restrict__ resid,
    int M, int N, int K, int ldc, int coff)
{
    __shared__ float As[2][8][128];
    __shared__ float Bs[2][8][128];
    int tid = threadIdx.x;
    int brow = blockIdx.y * 128;
    int bcol = blockIdx.x * 128;
    int arow = tid >> 1;
    int acol = (tid & 1) << 2;
    int brw = tid >> 5;
    int bcl = (tid & 31) << 2;
    int ty = tid >> 4, tx = tid & 15;
    float acc[8][8];
#pragma unroll
    for (int i = 0; i < 8; i++)
#pragma unroll
        for (int j = 0; j < 8; j++) acc[i][j] = 0.f;

    const float* Ap = A + (size_t)(brow + arow) * K + acol;
    const float* Wp = W + (size_t)brw * N + bcol + bcl;

    // preload tile 0 into buffer 0
    {
        float4 av = *(const float4*)(Ap);
        As[0][acol + 0][arow] = av.x;
        As[0][acol + 1][arow] = av.y;
        As[0][acol + 2][arow] = av.z;
        As[0][acol + 3][arow] = av.w;
        *(float4*)&Bs[0][brw][bcl] = *(const float4*)(Wp);
    }
    __syncthreads();

    int buf = 0;
    for (int k0 = 0; k0 < K; k0 += 8) {
        float4 av, bv;
        bool more = (k0 + 8) < K;
        if (more) {
            av = *(const float4*)(Ap + k0 + 8);
            bv = *(const float4*)(Wp + (size_t)(k0 + 8) * N);
        }
#pragma unroll
        for (int k = 0; k < 8; k++) {
            float4 a0 = *(const float4*)&As[buf][k][ty * 8];
            float4 a1 = *(const float4*)&As[buf][k][ty * 8 + 4];
            float4 b0 = *(const float4*)&Bs[buf][k][tx * 8];
            float4 b1 = *(const float4*)&Bs[buf][k][tx * 8 + 4];
            float ar[8] = {a0.x, a0.y, a0.z, a0.w, a1.x, a1.y, a1.z, a1.w};
            float br[8] = {b0.x, b0.y, b0.z, b0.w, b1.x, b1.y, b1.z, b1.w};
#pragma unroll
            for (int i = 0; i < 8; i++)
#pragma unroll
                for (int j = 0; j < 8; j++)
                    acc[i][j] = fmaf(ar[i], br[j], acc[i][j]);
        }
        if (more) {
            int nb = buf ^ 1;
            As[nb][acol + 0][arow] = av.x;
            As[nb][acol + 1][arow] = av.y;
            As[nb][acol + 2][arow] = av.z;
            As[nb][acol + 3][arow] = av.w;
            *(float4*)&Bs[nb][brw][bcl] = bv;
            __syncthreads();
            buf = nb;
        }
    }

#pragma unroll
    for (int i = 0; i < 8; i++) {
        int r = brow + ty * 8 + i;
        float* Crow = C + (size_t)r * ldc + coff + bcol;
#pragma unroll
        for (int j = 0; j < 8; j++) {
            int c = tx * 8 + j;
            float v = acc[i][j];
            if (MODE == EPI_STORE) {
                Crow[c] = v;
            } else if (MODE == EPI_ACCUM_BIAS) {
                Crow[c] += v + bias[bcol + c];
            } else if (MODE == EPI_GELU_BIAS) {
                v += bias[bcol + c];
                Crow[c] = 0.5f * v * (1.f + erff(v * 0.70710678118654752f));
            } else {  // EPI_BIAS_RESID
                Crow[c] = v + bias[bcol + c] + resid[(size_t)r * 384 + bcol + c];
            }
        }
    }
}

// ---------------- fused per-(sequence, head) attention ----------------
// qkv row layout: [q(384) | k(384) | v(384)], token row = b*768 + d*256 + h*16 + w
template <int T, int STRIDE, int AX>
__global__ void attn_kernel(const float* __restrict__ qkv, float* __restrict__ out)
{
    __shared__ float q[T][32], k[T][32], v[T][32], sc[T][T];
    int n = blockIdx.x;
    int head = blockIdx.y;
    int b, off;
    if (AX == 0) { b = n >> 8; off = n & 255; }                                        // fix (h,w), vary d
    else if (AX == 1) { b = n / 48; int r = n % 48; off = (r >> 4) * 256 + (r & 15); } // fix (d,w), vary h
    else { b = n / 48; int r = n % 48; off = (r >> 4) * 256 + (r & 15) * 16; }         // fix (d,h), vary w
    size_t base = (size_t)b * 768 + off;
    int tid = threadIdx.x;  // 128

    for (int idx = tid; idx < T * 32; idx += 128) {
        int ti = idx >> 5, d = idx & 31;
        size_t row = (base + (size_t)ti * STRIDE) * 1152;
        q[ti][d] = qkv[row + head * 32 + d];
        k[ti][d] = qkv[row + 384 + head * 32 + d];
        v[ti][d] = qkv[row + 768 + head * 32 + d];
    }
    __syncthreads();

    for (int idx = tid; idx < T * T; idx += 128) {
        int i = idx / T, j = idx % T;
        float s = 0.f;
#pragma unroll
        for (int d = 0; d < 32; d++) s = fmaf(q[i][d], k[j][d], s);
        sc[i][j] = s * 0.17677669529663687f;  // 1/sqrt(32)
    }
    __syncthreads();

    if (tid < T) {
        float mx = -1e30f;
#pragma unroll
        for (int j = 0; j < T; j++) mx = fmaxf(mx, sc[tid][j]);
        float e[T];
        float sum = 0.f;
#pragma unroll
        for (int j = 0; j < T; j++) { e[j] = expf(sc[tid][j] - mx); sum += e[j]; }
        float inv = 1.f / sum;
#pragma unroll
        for (int j = 0; j < T; j++) sc[tid][j] = e[j] * inv;
    }
    __syncthreads();

    for (int idx = tid; idx < T * 32; idx += 128) {
        int i = idx >> 5, d = idx & 31;
        float o = 0.f;
#pragma unroll
        for (int j = 0; j < T; j++) o = fmaf(sc[i][j], v[j][d], o);
        out[(base + (size_t)i * STRIDE) * 384 + head * 32 + d] = o;
    }
}

// ---------------- LayerNorm (warp per token, C=384) ----------------
__global__ void layernorm_kernel(const float* __restrict__ in, float* __restrict__ out,
                                 const float* __restrict__ g, const float* __restrict__ b)
{
    int row = blockIdx.x * (blockDim.x >> 5) + (threadIdx.x >> 5);
    int lane = threadIdx.x & 31;
    if (row >= MM) return;
    const float* rp = in + (size_t)row * 384;
    float vals[12];
    float sum = 0.f;
#pragma unroll
    for (int i = 0; i < 12; i++) { vals[i] = rp[lane + i * 32]; sum += vals[i]; }
#pragma unroll
    for (int o = 16; o; o >>= 1) sum += __shfl_xor_sync(0xffffffffu, sum, o);
    float mu = sum * (1.f / 384.f);
    float var = 0.f;
#pragma unroll
    for (int i = 0; i < 12; i++) { float d = vals[i] - mu; var = fmaf(d, d, var); }
#pragma unroll
    for (int o = 16; o; o >>= 1) var += __shfl_xor_sync(0xffffffffu, var, o);
    float inv = rsqrtf(var * (1.f / 384.f) + 1e-5f);
    float* op = out + (size_t)row * 384;
#pragma unroll
    for (int i = 0; i < 12; i++) {
        int c = lane + i * 32;
        op[c] = (vals[i] - mu) * inv * g[c] + b[c];
    }
}

// ---------------- launch ----------------
extern "C" void kernel_launch(void* const* d_in, const int* in_sizes, int n_in,
                              void* d_out, int out_size)
{
    const float* x = (const float*)d_in[0];
    const float* Wq[3]  = {(const float*)d_in[1], (const float*)d_in[5], (const float*)d_in[9]};
    const float* Wkv[3] = {(const float*)d_in[2], (const float*)d_in[6], (const float*)d_in[10]};
    const float* Wo[3]  = {(const float*)d_in[3], (const float*)d_in[7], (const float*)d_in[11]};
    const float* bo[3]  = {(const float*)d_in[4], (const float*)d_in[8], (const float*)d_in[12]};
    const float* g1  = (const float*)d_in[13];
    const float* be1 = (const float*)d_in[14];
    const float* W1m = (const float*)d_in[15];
    const float* b1m = (const float*)d_in[16];
    const float* W2m = (const float*)d_in[17];
    const float* b2m = (const float*)d_in[18];
    const float* g2  = (const float*)d_in[19];
    const float* be2 = (const float*)d_in[20];
    float* out = (float*)d_out;

    float *t0, *t1, *t2, *big;
    cudaGetSymbolAddress((void**)&t0, g_t0);
    cudaGetSymbolAddress((void**)&t1, g_t1);
    cudaGetSymbolAddress((void**)&t2, g_t2);
    cudaGetSymbolAddress((void**)&big, g_big);
    float* qkv = big;                          // MM x 1152
    float* ao  = big + (size_t)MM * 1152;      // MM x 384
    float* mlp = big;                          // MM x 1536 (after attention phase)
    float* t3  = t0;                           // t0 dead after attention phase

    dim3 tb(32, 8);
    transpose_in_kernel<<<dim3(SS / 32, CC / 32, BB), tb>>>(x, t0);

    for (int i = 0; i < 3; i++) {
        // qkv projections: q at col 0, k|v at col 384
        sgemm_kernel<EPI_STORE><<<dim3(3, MM / 128), 256>>>(t0, Wq[i], qkv, nullptr, nullptr,
                                                            MM, 384, 384, 1152, 0);
        sgemm_kernel<EPI_STORE><<<dim3(6, MM / 128), 256>>>(t0, Wkv[i], qkv, nullptr, nullptr,
                                                            MM, 768, 384, 1152, 384);
        if (i == 0)      attn_kernel<3, 256, 0><<<dim3(BB * 256, 12), 128>>>(qkv, ao);
        else if (i == 1) attn_kernel<16, 16, 1><<<dim3(BB * 48, 12), 128>>>(qkv, ao);
        else             attn_kernel<16, 1, 2><<<dim3(BB * 48, 12), 128>>>(qkv, ao);
        // o-projection; axial0 initializes t1 = t0 + o@Wo + bo, others accumulate
        if (i == 0)
            sgemm_kernel<EPI_BIAS_RESID><<<dim3(3, MM / 128), 256>>>(ao, Wo[i], t1, bo[i], t0,
                                                                     MM, 384, 384, 384, 0);
        else
            sgemm_kernel<EPI_ACCUM_BIAS><<<dim3(3, MM / 128), 256>>>(ao, Wo[i], t1, bo[i], nullptr,
                                                                     MM, 384, 384, 384, 0);
    }

    layernorm_kernel<<<MM / 8, 256>>>(t1, t2, g1, be1);
    sgemm_kernel<EPI_GELU_BIAS><<<dim3(12, MM / 128), 256>>>(t2, W1m, mlp, b1m, nullptr,
                                                             MM, 1536, 384, 1536, 0);
    sgemm_kernel<EPI_BIAS_RESID><<<dim3(3, MM / 128), 256>>>(mlp, W2m, t3, b2m, t2,
                                                             MM, 384, 1536, 384, 0);
    layernorm_kernel<<<MM / 8, 256>>>(t3, t1, g2, be2);

    transpose_out_kernel<<<dim3(SS / 32, CC / 32, BB), tb>>>(t1, out);
}

// round 5
// speedup vs baseline: 2.0678x; 2.0678x over previous
#include <cuda_runtime.h>
#include <cuda_bf16.h>
#include <math.h>
#include <stdint.h>

#define BB 128
#define SS 768
#define CC 384
#define MM (BB*SS)      // 98304 tokens

// ======================= low-level helpers (sm_80 ISA only) =======================
__device__ __forceinline__ uint32_t smem_to_u32(const void* smem_ptr) {
    uint32_t addr;
    asm("{ .reg .u64 tmp; cvta.to.shared.u64 tmp, %1; cvt.u32.u64 %0, tmp; }"
        : "=r"(addr) : "l"(smem_ptr));
    return addr;
}

#define CP_ASYNC16(dst32, gptr) \
    asm volatile("cp.async.cg.shared.global [%0], [%1], 16;" :: "r"(dst32), "l"(gptr) : "memory")
#define CP_COMMIT() asm volatile("cp.async.commit_group;" ::: "memory")

#define LDMATRIX_X4(r0, r1, r2, r3, addr) \
    asm volatile("ldmatrix.sync.aligned.m8n8.x4.shared.b16 {%0,%1,%2,%3}, [%4];" \
        : "=r"(r0), "=r"(r1), "=r"(r2), "=r"(r3) : "r"(addr))

#define MMA_BF16(d, a, b0, b1) \
    asm volatile("mma.sync.aligned.m16n8k16.row.col.f32.bf16.bf16.f32 " \
        "{%0,%1,%2,%3}, {%4,%5,%6,%7}, {%8,%9}, {%0,%1,%2,%3};" \
        : "+f"((d)[0]), "+f"((d)[1]), "+f"((d)[2]), "+f"((d)[3]) \
        : "r"((a)[0]), "r"((a)[1]), "r"((a)[2]), "r"((a)[3]), "r"(b0), "r"(b1))

__device__ __forceinline__ void split2(float x, __nv_bfloat16& h, __nv_bfloat16& l) {
    h = __float2bfloat16(x);
    l = __float2bfloat16(x - __bfloat162float(h));
}

// ======================= scratch (device globals) =======================
__device__ float g_t0f[(size_t)MM * CC];                 // tokens fp32 (also t3)
__device__ __nv_bfloat16 g_t0h[(size_t)MM * CC];
__device__ __nv_bfloat16 g_t0l[(size_t)MM * CC];
__device__ float g_t1f[(size_t)MM * CC];                 // residual accumulator / final LN out
__device__ float g_t2f[(size_t)MM * CC];                 // post-LN1 fp32 (resid for MLP2)
__device__ __nv_bfloat16 g_t2h[(size_t)MM * CC];
__device__ __nv_bfloat16 g_t2l[(size_t)MM * CC];
__device__ float g_big[(size_t)MM * 1536];               // qkv fp32 + ao hi/lo | mlp hi/lo
#define WTOTAL 2949120
__device__ __nv_bfloat16 g_wh[WTOTAL];
__device__ __nv_bfloat16 g_wl[WTOTAL];

// ======================= transposes =======================
// x (B, C, S) -> t0 (B*S, C) fp32 + hi/lo bf16
__global__ void transpose_in_kernel(const float* __restrict__ x, float* __restrict__ t0f,
                                    __nv_bfloat16* __restrict__ t0h, __nv_bfloat16* __restrict__ t0l) {
    __shared__ float tile[32][33];
    int b = blockIdx.z;
    int s0 = blockIdx.x * 32;
    int c0 = blockIdx.y * 32;
    int tx = threadIdx.x, ty = threadIdx.y;  // (32,8)
    const float* xp = x + (size_t)b * CC * SS;
#pragma unroll
    for (int yy = 0; yy < 32; yy += 8)
        tile[ty + yy][tx] = xp[(size_t)(c0 + ty + yy) * SS + s0 + tx];
    __syncthreads();
    size_t ob = (size_t)b * SS * CC;
#pragma unroll
    for (int yy = 0; yy < 32; yy += 8) {
        float v = tile[tx][ty + yy];
        size_t o = ob + (size_t)(s0 + ty + yy) * CC + c0 + tx;
        t0f[o] = v;
        __nv_bfloat16 h, l; split2(v, h, l);
        t0h[o] = h; t0l[o] = l;
    }
}

// t (B*S, C) -> out (B, C, S)
__global__ void transpose_out_kernel(const float* __restrict__ t, float* __restrict__ out) {
    __shared__ float tile[32][33];
    int b = blockIdx.z;
    int s0 = blockIdx.x * 32;
    int c0 = blockIdx.y * 32;
    int tx = threadIdx.x, ty = threadIdx.y;
    const float* tp = t + (size_t)b * SS * CC;
#pragma unroll
    for (int yy = 0; yy < 32; yy += 8)
        tile[ty + yy][tx] = tp[(size_t)(s0 + ty + yy) * CC + c0 + tx];
    __syncthreads();
    float* op = out + (size_t)b * CC * SS;
#pragma unroll
    for (int yy = 0; yy < 32; yy += 8)
        op[(size_t)(c0 + ty + yy) * SS + s0 + tx] = tile[tx][ty + yy];
}

// W [K,N] fp32 -> T [N,K] bf16 hi/lo (weight transpose + split)
__global__ void wsplit_kernel(const float* __restrict__ W, __nv_bfloat16* __restrict__ Th,
                              __nv_bfloat16* __restrict__ Tl, int K, int N) {
    __shared__ float tile[32][33];
    int n0 = blockIdx.x * 32;
    int k0 = blockIdx.y * 32;
    int tx = threadIdx.x, ty = threadIdx.y;  // (32,8)
#pragma unroll
    for (int yy = 0; yy < 32; yy += 8)
        tile[ty + yy][tx] = W[(size_t)(k0 + ty + yy) * N + n0 + tx];
    __syncthreads();
#pragma unroll
    for (int yy = 0; yy < 32; yy += 8) {
        float v = tile[tx][ty + yy];
        size_t o = (size_t)(n0 + ty + yy) * K + k0 + tx;
        __nv_bfloat16 h, l; split2(v, h, l);
        Th[o] = h; Tl[o] = l;
    }
}

// ======================= bf16x3 warp-mma GEMM =======================
// C[M,N] = A[M,K] * B^T, A [M,K] hi/lo bf16, B [N,K] hi/lo bf16 (both K-major).
// 3-pass split: Ah*Bh + Ah*Bl + Al*Bh, fp32 accumulate via mma.sync m16n8k16.
// Block tile 128x128, BK=32 (hi cols 0-31, lo cols 32-63 of a 64-bf16 = 128B smem row,
// 8x16B chunks XOR-swizzled), 2-stage cp.async pipeline, 8 warps (4x2) of 32x64 tiles.
enum { EPI_STORE = 0, EPI_ACCUM_BIAS = 1, EPI_GELU_BIAS = 2, EPI_BIAS_RESID = 3 };

#define GEMM_SMEM 65536   // 2 stages * (A 16KB + B 16KB)

__device__ __forceinline__ uint32_t sw_addr(uint32_t base, int row, int chunk) {
    return base + row * 128 + (((chunk ^ (row & 7)) << 4));
}

template <int MODE>
__device__ __forceinline__ void epi2(int R, int gc, float v0, float v1,
    float* Cf, __nv_bfloat16* Chi, __nv_bfloat16* Clo,
    const float* bias, const float* resid, int ldc)
{
    if (MODE == EPI_STORE) {
        *(float2*)(Cf + (size_t)R * ldc + gc) = make_float2(v0, v1);
    } else if (MODE == EPI_ACCUM_BIAS) {
        float* p = Cf + (size_t)R * ldc + gc;
        float2 o = *(float2*)p;
        o.x += v0 + bias[gc]; o.y += v1 + bias[gc + 1];
        *(float2*)p = o;
    } else if (MODE == EPI_GELU_BIAS) {
        float a0 = v0 + bias[gc], a1 = v1 + bias[gc + 1];
        a0 = 0.5f * a0 * (1.f + erff(a0 * 0.70710678118654752f));
        a1 = 0.5f * a1 * (1.f + erff(a1 * 0.70710678118654752f));
        __nv_bfloat16 h0, l0, h1, l1;
        split2(a0, h0, l0); split2(a1, h1, l1);
        *(__nv_bfloat162*)(Chi + (size_t)R * ldc + gc) = __halves2bfloat162(h0, h1);
        *(__nv_bfloat162*)(Clo + (size_t)R * ldc + gc) = __halves2bfloat162(l0, l1);
    } else {  // EPI_BIAS_RESID
        float2 rv = *(const float2*)(resid + (size_t)R * 384 + gc);
        *(float2*)(Cf + (size_t)R * ldc + gc) =
            make_float2(v0 + bias[gc] + rv.x, v1 + bias[gc + 1] + rv.y);
    }
}

template <int MODE>
__global__ __launch_bounds__(256) void mma_gemm(
    const __nv_bfloat16* __restrict__ Ah, const __nv_bfloat16* __restrict__ Al,
    const __nv_bfloat16* __restrict__ Bh, const __nv_bfloat16* __restrict__ Bl,
    float* __restrict__ Cf, __nv_bfloat16* __restrict__ Chi, __nv_bfloat16* __restrict__ Clo,
    const float* __restrict__ bias, const float* __restrict__ resid,
    int K, int ldc)
{
    extern __shared__ char smem_raw[];
    uint32_t sA = smem_to_u32(smem_raw);            // 2 x 16KB A stages
    uint32_t sB = sA + 32768;                        // 2 x 16KB B stages

    int tid = threadIdx.x, wid = tid >> 5, lane = tid & 31;
    int brow = blockIdx.y * 128, bcol = blockIdx.x * 128;
    int warpM = wid & 3, warpN = wid >> 2;           // 4x2 warp grid, tile 32x64
    int lg = lane >> 3, lr = lane & 7;               // ldmatrix address group / row

    // cp.async stage loader: 256 threads x 4 iters x (1 A-chunk + 1 B-chunk) of 16B
    auto load_stage = [&](int s, int k0) {
#pragma unroll
        for (int i = 0; i < 4; i++) {
            int lin = tid + (i << 8);
            int row = lin >> 3, cc = lin & 7;        // cc 0-3 = hi, 4-7 = lo
            int kof = k0 + (cc & 3) * 8;
            const __nv_bfloat16* ga = ((cc < 4) ? Ah : Al) + (size_t)(brow + row) * K + kof;
            CP_ASYNC16(sw_addr(sA + s * 16384, row, cc), ga);
            const __nv_bfloat16* gb = ((cc < 4) ? Bh : Bl) + (size_t)(bcol + row) * K + kof;
            CP_ASYNC16(sw_addr(sB + s * 16384, row, cc), gb);
        }
        CP_COMMIT();
    };

    float acc[2][8][4];
#pragma unroll
    for (int mt = 0; mt < 2; mt++)
#pragma unroll
        for (int nt = 0; nt < 8; nt++)
#pragma unroll
            for (int r = 0; r < 4; r++) acc[mt][nt][r] = 0.f;

    int nstage = K >> 5;
    load_stage(0, 0);

    for (int st = 0; st < nstage; st++) {
        if (st + 1 < nstage) {
            load_stage((st + 1) & 1, (st + 1) << 5);
            asm volatile("cp.async.wait_group 1;" ::: "memory");
        } else {
            asm volatile("cp.async.wait_group 0;" ::: "memory");
        }
        __syncthreads();

        uint32_t bA = sA + (st & 1) * 16384;
        uint32_t bBs = sB + (st & 1) * 16384;
#pragma unroll
        for (int kk = 0; kk < 2; kk++) {
            int c0h = kk * 2, c0l = 4 + kk * 2;
            uint32_t ah[2][4], al[2][4];
#pragma unroll
            for (int mt = 0; mt < 2; mt++) {
                int m0 = warpM * 32 + mt * 16;
                int rowoff = ((lg & 1) ? 8 : 0) + lr;
                int chs = lg >> 1;
                LDMATRIX_X4(ah[mt][0], ah[mt][1], ah[mt][2], ah[mt][3],
                            sw_addr(bA, m0 + rowoff, c0h + chs));
                LDMATRIX_X4(al[mt][0], al[mt][1], al[mt][2], al[mt][3],
                            sw_addr(bA, m0 + rowoff, c0l + chs));
            }
            uint32_t bh[4][4], bl[4][4];
#pragma unroll
            for (int np = 0; np < 4; np++) {
                int n0 = warpN * 64 + np * 16;
                int rowoff = ((lg >> 1) ? 8 : 0) + lr;
                int chs = lg & 1;
                LDMATRIX_X4(bh[np][0], bh[np][1], bh[np][2], bh[np][3],
                            sw_addr(bBs, n0 + rowoff, c0h + chs));
                LDMATRIX_X4(bl[np][0], bl[np][1], bl[np][2], bl[np][3],
                            sw_addr(bBs, n0 + rowoff, c0l + chs));
            }
#pragma unroll
            for (int mt = 0; mt < 2; mt++)
#pragma unroll
                for (int nt = 0; nt < 8; nt++) {
                    uint32_t b0h = bh[nt >> 1][(nt & 1) * 2], b1h = bh[nt >> 1][(nt & 1) * 2 + 1];
                    uint32_t b0l = bl[nt >> 1][(nt & 1) * 2], b1l = bl[nt >> 1][(nt & 1) * 2 + 1];
                    MMA_BF16(acc[mt][nt], ah[mt], b0h, b1h);
                    MMA_BF16(acc[mt][nt], ah[mt], b0l, b1l);
                    MMA_BF16(acc[mt][nt], al[mt], b0h, b1h);
                }
        }
        __syncthreads();
    }

    // epilogue straight from registers
#pragma unroll
    for (int mt = 0; mt < 2; mt++)
#pragma unroll
        for (int nt = 0; nt < 8; nt++) {
            int R0 = brow + warpM * 32 + mt * 16 + (lane >> 2);
            int gc = bcol + warpN * 64 + nt * 8 + ((lane & 3) << 1);
            epi2<MODE>(R0,     gc, acc[mt][nt][0], acc[mt][nt][1], Cf, Chi, Clo, bias, resid, ldc);
            epi2<MODE>(R0 + 8, gc, acc[mt][nt][2], acc[mt][nt][3], Cf, Chi, Clo, bias, resid, ldc);
        }
}

// ======================= fused per-(sequence, head) attention =======================
// qkv row layout: [q(384) | k(384) | v(384)], token row = b*768 + d*256 + h*16 + w
template <int T, int STRIDE, int AX>
__global__ void attn_kernel(const float* __restrict__ qkv,
                            __nv_bfloat16* __restrict__ aoh, __nv_bfloat16* __restrict__ aol)
{
    __shared__ float q[T][32], k[T][32], v[T][32], sc[T][T];
    int n = blockIdx.x;
    int head = blockIdx.y;
    int b, off;
    if (AX == 0) { b = n >> 8; off = n & 255; }
    else if (AX == 1) { b = n / 48; int r = n % 48; off = (r >> 4) * 256 + (r & 15); }
    else { b = n / 48; int r = n % 48; off = (r >> 4) * 256 + (r & 15) * 16; }
    size_t base = (size_t)b * 768 + off;
    int tid = threadIdx.x;  // 128

    for (int idx = tid; idx < T * 32; idx += 128) {
        int ti = idx >> 5, d = idx & 31;
        size_t row = (base + (size_t)ti * STRIDE) * 1152;
        q[ti][d] = qkv[row + head * 32 + d];
        k[ti][d] = qkv[row + 384 + head * 32 + d];
        v[ti][d] = qkv[row + 768 + head * 32 + d];
    }
    __syncthreads();

    for (int idx = tid; idx < T * T; idx += 128) {
        int i = idx / T, j = idx % T;
        float s = 0.f;
#pragma unroll
        for (int d = 0; d < 32; d++) s = fmaf(q[i][d], k[j][d], s);
        sc[i][j] = s * 0.17677669529663687f;
    }
    __syncthreads();

    if (tid < T) {
        float mx = -1e30f;
#pragma unroll
        for (int j = 0; j < T; j++) mx = fmaxf(mx, sc[tid][j]);
        float e[T];
        float sum = 0.f;
#pragma unroll
        for (int j = 0; j < T; j++) { e[j] = expf(sc[tid][j] - mx); sum += e[j]; }
        float inv = 1.f / sum;
#pragma unroll
        for (int j = 0; j < T; j++) sc[tid][j] = e[j] * inv;
    }
    __syncthreads();

    for (int idx = tid; idx < T * 32; idx += 128) {
        int i = idx >> 5, d = idx & 31;
        float o = 0.f;
#pragma unroll
        for (int j = 0; j < T; j++) o = fmaf(sc[i][j], v[j][d], o);
        size_t oi = (base + (size_t)i * STRIDE) * 384 + head * 32 + d;
        __nv_bfloat16 h, l; split2(o, h, l);
        aoh[oi] = h; aol[oi] = l;
    }
}

// ======================= LayerNorm (warp per token) =======================
template <bool SPLIT>
__global__ void layernorm_kernel(const float* __restrict__ in, float* __restrict__ outf,
                                 __nv_bfloat16* __restrict__ outh, __nv_bfloat16* __restrict__ outl,
                                 const float* __restrict__ g, const float* __restrict__ b)
{
    int row = blockIdx.x * (blockDim.x >> 5) + (threadIdx.x >> 5);
    int lane = threadIdx.x & 31;
    if (row >= MM) return;
    const float* rp = in + (size_t)row * 384;
    float vals[12];
    float sum = 0.f;
#pragma unroll
    for (int i = 0; i < 12; i++) { vals[i] = rp[lane + i * 32]; sum += vals[i]; }
#pragma unroll
    for (int o = 16; o; o >>= 1) sum += __shfl_xor_sync(0xffffffffu, sum, o);
    float mu = sum * (1.f / 384.f);
    float var = 0.f;
#pragma unroll
    for (int i = 0; i < 12; i++) { float d = vals[i] - mu; var = fmaf(d, d, var); }
#pragma unroll
    for (int o = 16; o; o >>= 1) var += __shfl_xor_sync(0xffffffffu, var, o);
    float inv = rsqrtf(var * (1.f / 384.f) + 1e-5f);
#pragma unroll
    for (int i = 0; i < 12; i++) {
        int c = lane + i * 32;
        float y = (vals[i] - mu) * inv * g[c] + b[c];
        size_t o = (size_t)row * 384 + c;
        outf[o] = y;
        if (SPLIT) {
            __nv_bfloat16 h, l; split2(y, h, l);
            outh[o] = h; outl[o] = l;
        }
    }
}

// ======================= launch =======================
extern "C" void kernel_launch(void* const* d_in, const int* in_sizes, int n_in,
                              void* d_out, int out_size)
{
    const float* x = (const float*)d_in[0];
    const float* Wq[3]  = {(const float*)d_in[1], (const float*)d_in[5], (const float*)d_in[9]};
    const float* Wkv[3] = {(const float*)d_in[2], (const float*)d_in[6], (const float*)d_in[10]};
    const float* Wo[3]  = {(const float*)d_in[3], (const float*)d_in[7], (const float*)d_in[11]};
    const float* bo[3]  = {(const float*)d_in[4], (const float*)d_in[8], (const float*)d_in[12]};
    const float* g1  = (const float*)d_in[13];
    const float* be1 = (const float*)d_in[14];
    const float* W1m = (const float*)d_in[15];
    const float* b1m = (const float*)d_in[16];
    const float* W2m = (const float*)d_in[17];
    const float* b2m = (const float*)d_in[18];
    const float* g2  = (const float*)d_in[19];
    const float* be2 = (const float*)d_in[20];
    float* out = (float*)d_out;

    float *t0f, *t1f, *t2f, *big;
    __nv_bfloat16 *t0h, *t0l, *t2h, *t2l, *wh, *wl;
    cudaGetSymbolAddress((void**)&t0f, g_t0f);
    cudaGetSymbolAddress((void**)&t0h, g_t0h);
    cudaGetSymbolAddress((void**)&t0l, g_t0l);
    cudaGetSymbolAddress((void**)&t1f, g_t1f);
    cudaGetSymbolAddress((void**)&t2f, g_t2f);
    cudaGetSymbolAddress((void**)&t2h, g_t2h);
    cudaGetSymbolAddress((void**)&t2l, g_t2l);
    cudaGetSymbolAddress((void**)&big, g_big);
    cudaGetSymbolAddress((void**)&wh, g_wh);
    cudaGetSymbolAddress((void**)&wl, g_wl);

    float* qkvf = big;                                       // MM x 1152 fp32
    __nv_bfloat16* aoh = (__nv_bfloat16*)(big + (size_t)MM * 1152);
    __nv_bfloat16* aol = aoh + (size_t)MM * 384;
    __nv_bfloat16* mlph = (__nv_bfloat16*)big;               // MM x 1536 (MLP phase)
    __nv_bfloat16* mlpl = mlph + (size_t)MM * 1536;
    float* t3f = t0f;                                        // t0 dead after attention

    // weight pool offsets (elements): per axial i, [Wqkv_t 1152x384] then Wo_t, W1m_t, W2m_t
    const size_t QKV_OFF = 442368;   // 1152*384
    const size_t O_BASE  = 3 * QKV_OFF;          // 1327104
    const size_t O_SZ    = 147456;               // 384*384
    const size_t W1_OFF  = O_BASE + 3 * O_SZ;    // 1769472
    const size_t W2_OFF  = W1_OFF + 589824;      // 2359296

    cudaFuncSetAttribute(mma_gemm<EPI_STORE>,      cudaFuncAttributeMaxDynamicSharedMemorySize, GEMM_SMEM);
    cudaFuncSetAttribute(mma_gemm<EPI_ACCUM_BIAS>, cudaFuncAttributeMaxDynamicSharedMemorySize, GEMM_SMEM);
    cudaFuncSetAttribute(mma_gemm<EPI_GELU_BIAS>,  cudaFuncAttributeMaxDynamicSharedMemorySize, GEMM_SMEM);
    cudaFuncSetAttribute(mma_gemm<EPI_BIAS_RESID>, cudaFuncAttributeMaxDynamicSharedMemorySize, GEMM_SMEM);

    dim3 tb(32, 8);
    // weight transpose + split
    for (int i = 0; i < 3; i++) {
        wsplit_kernel<<<dim3(384 / 32, 384 / 32), tb>>>(Wq[i],  wh + i * QKV_OFF,          wl + i * QKV_OFF,          384, 384);
        wsplit_kernel<<<dim3(768 / 32, 384 / 32), tb>>>(Wkv[i], wh + i * QKV_OFF + 147456, wl + i * QKV_OFF + 147456, 384, 768);
        wsplit_kernel<<<dim3(384 / 32, 384 / 32), tb>>>(Wo[i],  wh + O_BASE + i * O_SZ,    wl + O_BASE + i * O_SZ,    384, 384);
    }
    wsplit_kernel<<<dim3(1536 / 32, 384 / 32), tb>>>(W1m, wh + W1_OFF, wl + W1_OFF, 384, 1536);
    wsplit_kernel<<<dim3(384 / 32, 1536 / 32), tb>>>(W2m, wh + W2_OFF, wl + W2_OFF, 1536, 384);

    transpose_in_kernel<<<dim3(SS / 32, CC / 32, BB), tb>>>(x, t0f, t0h, t0l);

    for (int i = 0; i < 3; i++) {
        // fused qkv projection: N=1152 (Wq_t rows 0-383, Wkv_t rows 384-1151)
        mma_gemm<EPI_STORE><<<dim3(9, MM / 128), 256, GEMM_SMEM>>>(
            t0h, t0l, wh + i * QKV_OFF, wl + i * QKV_OFF,
            qkvf, nullptr, nullptr, nullptr, nullptr, 384, 1152);
        if (i == 0)      attn_kernel<3, 256, 0><<<dim3(BB * 256, 12), 128>>>(qkvf, aoh, aol);
        else if (i == 1) attn_kernel<16, 16, 1><<<dim3(BB * 48, 12), 128>>>(qkvf, aoh, aol);
        else             attn_kernel<16, 1, 2><<<dim3(BB * 48, 12), 128>>>(qkvf, aoh, aol);
        if (i == 0)
            mma_gemm<EPI_BIAS_RESID><<<dim3(3, MM / 128), 256, GEMM_SMEM>>>(
                aoh, aol, wh + O_BASE, wl + O_BASE,
                t1f, nullptr, nullptr, bo[0], t0f, 384, 384);
        else
            mma_gemm<EPI_ACCUM_BIAS><<<dim3(3, MM / 128), 256, GEMM_SMEM>>>(
                aoh, aol, wh + O_BASE + i * O_SZ, wl + O_BASE + i * O_SZ,
                t1f, nullptr, nullptr, bo[i], nullptr, 384, 384);
    }

    layernorm_kernel<true><<<MM / 8, 256>>>(t1f, t2f, t2h, t2l, g1, be1);
    mma_gemm<EPI_GELU_BIAS><<<dim3(12, MM / 128), 256, GEMM_SMEM>>>(
        t2h, t2l, wh + W1_OFF, wl + W1_OFF,
        nullptr, mlph, mlpl, b1m, nullptr, 384, 1536);
    mma_gemm<EPI_BIAS_RESID><<<dim3(3, MM / 128), 256, GEMM_SMEM>>>(
        mlph, mlpl, wh + W2_OFF, wl + W2_OFF,
        t3f, nullptr, nullptr, b2m, t2f, 1536, 384);
    layernorm_kernel<false><<<MM / 8, 256>>>(t3f, t1f, nullptr, nullptr, g2, be2);

    transpose_out_kernel<<<dim3(SS / 32, CC / 32, BB), tb>>>(t1f, out);
}

// round 6
// speedup vs baseline: 4.3517x; 2.1045x over previous
#include <cuda_runtime.h>
#include <cuda_fp16.h>
#include <math.h>
#include <stdint.h>

#define BB 128
#define SS 768
#define CC 384
#define MM (BB*SS)      // 98304 tokens

// ======================= low-level helpers (sm_80 ISA only) =======================
__device__ __forceinline__ uint32_t smem_to_u32(const void* smem_ptr) {
    uint32_t addr;
    asm("{ .reg .u64 tmp; cvta.to.shared.u64 tmp, %1; cvt.u32.u64 %0, tmp; }"
        : "=r"(addr) : "l"(smem_ptr));
    return addr;
}

#define CP_ASYNC16(dst32, gptr) \
    asm volatile("cp.async.cg.shared.global [%0], [%1], 16;" :: "r"(dst32), "l"(gptr) : "memory")
#define CP_COMMIT() asm volatile("cp.async.commit_group;" ::: "memory")

#define LDMATRIX_X4(r0, r1, r2, r3, addr) \
    asm volatile("ldmatrix.sync.aligned.m8n8.x4.shared.b16 {%0,%1,%2,%3}, [%4];" \
        : "=r"(r0), "=r"(r1), "=r"(r2), "=r"(r3) : "r"(addr))

#define MMA_F16(d, a, b0, b1) \
    asm volatile("mma.sync.aligned.m16n8k16.row.col.f32.f16.f16.f32 " \
        "{%0,%1,%2,%3}, {%4,%5,%6,%7}, {%8,%9}, {%0,%1,%2,%3};" \
        : "+f"((d)[0]), "+f"((d)[1]), "+f"((d)[2]), "+f"((d)[3]) \
        : "r"((a)[0]), "r"((a)[1]), "r"((a)[2]), "r"((a)[3]), "r"(b0), "r"(b1))

// ======================= scratch (device globals) =======================
__device__ float g_t0f[(size_t)MM * CC];                 // tokens fp32 (also t3)
__device__ __half g_t0h[(size_t)MM * CC];                // tokens fp16 (GEMM A)
__device__ float g_t1f[(size_t)MM * CC];                 // residual accumulator / final LN out
__device__ float g_t2f[(size_t)MM * CC];                 // post-LN1 fp32 (resid for MLP2)
__device__ __half g_t2h[(size_t)MM * CC];                // post-LN1 fp16
__device__ float g_big[(size_t)MM * 1536];               // qkv fp32 + ao fp16 | mlp fp16
#define WTOTAL 2949120
__device__ __half g_wh[WTOTAL];                          // transposed fp16 weights

// ======================= transposes =======================
// x (B, C, S) -> t0 (B*S, C) fp32 + fp16
__global__ void transpose_in_kernel(const float* __restrict__ x, float* __restrict__ t0f,
                                    __half* __restrict__ t0h) {
    __shared__ float tile[32][33];
    int b = blockIdx.z;
    int s0 = blockIdx.x * 32;
    int c0 = blockIdx.y * 32;
    int tx = threadIdx.x, ty = threadIdx.y;  // (32,8)
    const float* xp = x + (size_t)b * CC * SS;
#pragma unroll
    for (int yy = 0; yy < 32; yy += 8)
        tile[ty + yy][tx] = xp[(size_t)(c0 + ty + yy) * SS + s0 + tx];
    __syncthreads();
    size_t ob = (size_t)b * SS * CC;
#pragma unroll
    for (int yy = 0; yy < 32; yy += 8) {
        float v = tile[tx][ty + yy];
        size_t o = ob + (size_t)(s0 + ty + yy) * CC + c0 + tx;
        t0f[o] = v;
        t0h[o] = __float2half(v);
    }
}

// t (B*S, C) -> out (B, C, S)
__global__ void transpose_out_kernel(const float* __restrict__ t, float* __restrict__ out) {
    __shared__ float tile[32][33];
    int b = blockIdx.z;
    int s0 = blockIdx.x * 32;
    int c0 = blockIdx.y * 32;
    int tx = threadIdx.x, ty = threadIdx.y;
    const float* tp = t + (size_t)b * SS * CC;
#pragma unroll
    for (int yy = 0; yy < 32; yy += 8)
        tile[ty + yy][tx] = tp[(size_t)(s0 + ty + yy) * CC + c0 + tx];
    __syncthreads();
    float* op = out + (size_t)b * CC * SS;
#pragma unroll
    for (int yy = 0; yy < 32; yy += 8)
        op[(size_t)(c0 + ty + yy) * SS + s0 + tx] = tile[tx][ty + yy];
}

// W [K,N] fp32 -> T [N,K] fp16 (weight transpose + convert)
__global__ void wconv_kernel(const float* __restrict__ W, __half* __restrict__ T,
                             int K, int N) {
    __shared__ float tile[32][33];
    int n0 = blockIdx.x * 32;
    int k0 = blockIdx.y * 32;
    int tx = threadIdx.x, ty = threadIdx.y;  // (32,8)
#pragma unroll
    for (int yy = 0; yy < 32; yy += 8)
        tile[ty + yy][tx] = W[(size_t)(k0 + ty + yy) * N + n0 + tx];
    __syncthreads();
#pragma unroll
    for (int yy = 0; yy < 32; yy += 8)
        T[(size_t)(n0 + ty + yy) * K + k0 + tx] = __float2half(tile[tx][ty + yy]);
}

// ======================= fp16 warp-mma GEMM =======================
// C[M,N] = A[M,K] * B^T, A [M,K] fp16, B [N,K] fp16 (both K-major).
// Block tile 128x128, BK=64 (64 fp16 = one 128B smem row, 8x16B XOR-swizzled chunks),
// 2-stage cp.async pipeline, 8 warps (4x2) each computing 32x64 via m16n8k16.
enum { EPI_STORE = 0, EPI_ACCUM_BIAS = 1, EPI_GELU_BIAS = 2, EPI_BIAS_RESID = 3 };

#define GEMM_SMEM 65536   // 2 stages * (A 16KB + B 16KB)

__device__ __forceinline__ uint32_t sw_addr(uint32_t base, int row, int chunk) {
    return base + row * 128 + (((chunk ^ (row & 7)) << 4));
}

template <int MODE>
__device__ __forceinline__ void epi2(int R, int gc, float v0, float v1,
    float* Cf, __half* Ch, const float* bias, const float* resid, int ldc)
{
    if (MODE == EPI_STORE) {
        *(float2*)(Cf + (size_t)R * ldc + gc) = make_float2(v0, v1);
    } else if (MODE == EPI_ACCUM_BIAS) {
        float* p = Cf + (size_t)R * ldc + gc;
        float2 o = *(float2*)p;
        o.x += v0 + bias[gc]; o.y += v1 + bias[gc + 1];
        *(float2*)p = o;
    } else if (MODE == EPI_GELU_BIAS) {
        float a0 = v0 + bias[gc], a1 = v1 + bias[gc + 1];
        a0 = 0.5f * a0 * (1.f + erff(a0 * 0.70710678118654752f));
        a1 = 0.5f * a1 * (1.f + erff(a1 * 0.70710678118654752f));
        *(__half2*)(Ch + (size_t)R * ldc + gc) = __floats2half2_rn(a0, a1);
    } else {  // EPI_BIAS_RESID
        float2 rv = *(const float2*)(resid + (size_t)R * 384 + gc);
        *(float2*)(Cf + (size_t)R * ldc + gc) =
            make_float2(v0 + bias[gc] + rv.x, v1 + bias[gc + 1] + rv.y);
    }
}

template <int MODE>
__global__ __launch_bounds__(256) void mma_gemm(
    const __half* __restrict__ Ah, const __half* __restrict__ Bh,
    float* __restrict__ Cf, __half* __restrict__ Ch,
    const float* __restrict__ bias, const float* __restrict__ resid,
    int K, int ldc)
{
    extern __shared__ char smem_raw[];
    uint32_t sA = smem_to_u32(smem_raw);            // 2 x 16KB A stages
    uint32_t sB = sA + 32768;                        // 2 x 16KB B stages

    int tid = threadIdx.x, wid = tid >> 5, lane = tid & 31;
    int brow = blockIdx.y * 128, bcol = blockIdx.x * 128;
    int warpM = wid & 3, warpN = wid >> 2;           // 4x2 warp grid, tile 32x64
    int lg = lane >> 3, lr = lane & 7;               // ldmatrix address group / row

    // stage loader: 128 rows x 64 fp16 per operand, 8 x 16B chunks per row
    auto load_stage = [&](int s, int k0) {
#pragma unroll
        for (int i = 0; i < 4; i++) {
            int lin = tid + (i << 8);
            int row = lin >> 3, cc = lin & 7;
            int kof = k0 + cc * 8;
            CP_ASYNC16(sw_addr(sA + s * 16384, row, cc),
                       Ah + (size_t)(brow + row) * K + kof);
            CP_ASYNC16(sw_addr(sB + s * 16384, row, cc),
                       Bh + (size_t)(bcol + row) * K + kof);
        }
        CP_COMMIT();
    };

    float acc[2][8][4];
#pragma unroll
    for (int mt = 0; mt < 2; mt++)
#pragma unroll
        for (int nt = 0; nt < 8; nt++)
#pragma unroll
            for (int r = 0; r < 4; r++) acc[mt][nt][r] = 0.f;

    int nstage = K >> 6;
    load_stage(0, 0);

    for (int st = 0; st < nstage; st++) {
        if (st + 1 < nstage) {
            load_stage((st + 1) & 1, (st + 1) << 6);
            asm volatile("cp.async.wait_group 1;" ::: "memory");
        } else {
            asm volatile("cp.async.wait_group 0;" ::: "memory");
        }
        __syncthreads();

        uint32_t bA = sA + (st & 1) * 16384;
        uint32_t bBs = sB + (st & 1) * 16384;
#pragma unroll
        for (int kk = 0; kk < 4; kk++) {
            int c0 = kk * 2;
            uint32_t af[2][4];
#pragma unroll
            for (int mt = 0; mt < 2; mt++) {
                int m0 = warpM * 32 + mt * 16;
                int rowoff = ((lg & 1) ? 8 : 0) + lr;
                int chs = lg >> 1;
                LDMATRIX_X4(af[mt][0], af[mt][1], af[mt][2], af[mt][3],
                            sw_addr(bA, m0 + rowoff, c0 + chs));
            }
            uint32_t bf[4][4];
#pragma unroll
            for (int np = 0; np < 4; np++) {
                int n0 = warpN * 64 + np * 16;
                int rowoff = ((lg >> 1) ? 8 : 0) + lr;
                int chs = lg & 1;
                LDMATRIX_X4(bf[np][0], bf[np][1], bf[np][2], bf[np][3],
                            sw_addr(bBs, n0 + rowoff, c0 + chs));
            }
#pragma unroll
            for (int mt = 0; mt < 2; mt++)
#pragma unroll
                for (int nt = 0; nt < 8; nt++) {
                    uint32_t b0 = bf[nt >> 1][(nt & 1) * 2], b1 = bf[nt >> 1][(nt & 1) * 2 + 1];
                    MMA_F16(acc[mt][nt], af[mt], b0, b1);
                }
        }
        __syncthreads();
    }

    // epilogue straight from registers
#pragma unroll
    for (int mt = 0; mt < 2; mt++)
#pragma unroll
        for (int nt = 0; nt < 8; nt++) {
            int R0 = brow + warpM * 32 + mt * 16 + (lane >> 2);
            int gc = bcol + warpN * 64 + nt * 8 + ((lane & 3) << 1);
            epi2<MODE>(R0,     gc, acc[mt][nt][0], acc[mt][nt][1], Cf, Ch, bias, resid, ldc);
            epi2<MODE>(R0 + 8, gc, acc[mt][nt][2], acc[mt][nt][3], Cf, Ch, bias, resid, ldc);
        }
}

// ======================= attention =======================
// qkv row layout: [q(384) | k(384) | v(384)], token row = b*768 + d*256 + h*16 + w

// Axial 0 (T=3, stride 256): one block per (b, h, w) position, all 12 heads.
__global__ void attn3_kernel(const float* __restrict__ qkv, __half* __restrict__ ao)
{
    __shared__ float s[3][1152];
    __shared__ float p[12][3][3];
    int n = blockIdx.x;
    int b = n >> 8, off = n & 255;
    size_t base = (size_t)b * 768 + off;
    int tid = threadIdx.x;  // 128

    for (int idx = tid; idx < 3 * 1152; idx += 128) {
        int ti = idx / 1152, c = idx % 1152;
        s[ti][c] = qkv[(base + (size_t)ti * 256) * 1152 + c];
    }
    __syncthreads();

    if (tid < 108) {
        int h = tid / 9, r = tid % 9, i = r / 3, j = r % 3;
        float a = 0.f;
#pragma unroll
        for (int d = 0; d < 32; d++) a = fmaf(s[i][h * 32 + d], s[j][384 + h * 32 + d], a);
        p[h][i][j] = a * 0.17677669529663687f;
    }
    __syncthreads();

    if (tid < 36) {
        int h = tid / 3, i = tid % 3;
        float m = fmaxf(p[h][i][0], fmaxf(p[h][i][1], p[h][i][2]));
        float e0 = expf(p[h][i][0] - m), e1 = expf(p[h][i][1] - m), e2 = expf(p[h][i][2] - m);
        float inv = 1.f / (e0 + e1 + e2);
        p[h][i][0] = e0 * inv; p[h][i][1] = e1 * inv; p[h][i][2] = e2 * inv;
    }
    __syncthreads();

    for (int idx = tid; idx < 3 * 384; idx += 128) {
        int i = idx / 384, c = idx % 384, h = c >> 5;
        float o = p[h][i][0] * s[0][768 + c] + p[h][i][1] * s[1][768 + c]
                + p[h][i][2] * s[2][768 + c];
        ao[(base + (size_t)i * 256) * 384 + c] = __float2half(o);
    }
}

// Axials 1/2 (T=16): one block per (sequence, head).
template <int STRIDE, int AX>
__global__ void attn16_kernel(const float* __restrict__ qkv, __half* __restrict__ ao)
{
    const int T = 16;
    __shared__ float q[T][32], k[T][32], v[T][32], sc[T][T];
    int n = blockIdx.x;
    int head = blockIdx.y;
    int b = n / 48, r = n % 48;
    int off = (AX == 1) ? ((r >> 4) * 256 + (r & 15)) : ((r >> 4) * 256 + (r & 15) * 16);
    size_t base = (size_t)b * 768 + off;
    int tid = threadIdx.x;  // 128

    for (int idx = tid; idx < T * 32; idx += 128) {
        int ti = idx >> 5, d = idx & 31;
        size_t row = (base + (size_t)ti * STRIDE) * 1152;
        q[ti][d] = qkv[row + head * 32 + d];
        k[ti][d] = qkv[row + 384 + head * 32 + d];
        v[ti][d] = qkv[row + 768 + head * 32 + d];
    }
    __syncthreads();

    for (int idx = tid; idx < T * T; idx += 128) {
        int i = idx >> 4, j = idx & 15;
        float s = 0.f;
#pragma unroll
        for (int d = 0; d < 32; d++) s = fmaf(q[i][d], k[j][d], s);
        sc[i][j] = s * 0.17677669529663687f;
    }
    __syncthreads();

    if (tid < T) {
        float mx = -1e30f;
#pragma unroll
        for (int j = 0; j < T; j++) mx = fmaxf(mx, sc[tid][j]);
        float e[T];
        float sum = 0.f;
#pragma unroll
        for (int j = 0; j < T; j++) { e[j] = expf(sc[tid][j] - mx); sum += e[j]; }
        float inv = 1.f / sum;
#pragma unroll
        for (int j = 0; j < T; j++) sc[tid][j] = e[j] * inv;
    }
    __syncthreads();

    for (int idx = tid; idx < T * 32; idx += 128) {
        int i = idx >> 5, d = idx & 31;
        float o = 0.f;
#pragma unroll
        for (int j = 0; j < T; j++) o = fmaf(sc[i][j], v[j][d], o);
        ao[(base + (size_t)i * STRIDE) * 384 + head * 32 + d] = __float2half(o);
    }
}

// ======================= LayerNorm (warp per token) =======================
template <bool SPLIT>
__global__ void layernorm_kernel(const float* __restrict__ in, float* __restrict__ outf,
                                 __half* __restrict__ outh,
                                 const float* __restrict__ g, const float* __restrict__ b)
{
    int row = blockIdx.x * (blockDim.x >> 5) + (threadIdx.x >> 5);
    int lane = threadIdx.x & 31;
    if (row >= MM) return;
    const float* rp = in + (size_t)row * 384;
    float vals[12];
    float sum = 0.f;
#pragma unroll
    for (int i = 0; i < 12; i++) { vals[i] = rp[lane + i * 32]; sum += vals[i]; }
#pragma unroll
    for (int o = 16; o; o >>= 1) sum += __shfl_xor_sync(0xffffffffu, sum, o);
    float mu = sum * (1.f / 384.f);
    float var = 0.f;
#pragma unroll
    for (int i = 0; i < 12; i++) { float d = vals[i] - mu; var = fmaf(d, d, var); }
#pragma unroll
    for (int o = 16; o; o >>= 1) var += __shfl_xor_sync(0xffffffffu, var, o);
    float inv = rsqrtf(var * (1.f / 384.f) + 1e-5f);
#pragma unroll
    for (int i = 0; i < 12; i++) {
        int c = lane + i * 32;
        float y = (vals[i] - mu) * inv * g[c] + b[c];
        size_t o = (size_t)row * 384 + c;
        outf[o] = y;
        if (SPLIT) outh[o] = __float2half(y);
    }
}

// ======================= launch =======================
extern "C" void kernel_launch(void* const* d_in, const int* in_sizes, int n_in,
                              void* d_out, int out_size)
{
    const float* x = (const float*)d_in[0];
    const float* Wq[3]  = {(const float*)d_in[1], (const float*)d_in[5], (const float*)d_in[9]};
    const float* Wkv[3] = {(const float*)d_in[2], (const float*)d_in[6], (const float*)d_in[10]};
    const float* Wo[3]  = {(const float*)d_in[3], (const float*)d_in[7], (const float*)d_in[11]};
    const float* bo[3]  = {(const float*)d_in[4], (const float*)d_in[8], (const float*)d_in[12]};
    const float* g1  = (const float*)d_in[13];
    const float* be1 = (const float*)d_in[14];
    const float* W1m = (const float*)d_in[15];
    const float* b1m = (const float*)d_in[16];
    const float* W2m = (const float*)d_in[17];
    const float* b2m = (const float*)d_in[18];
    const float* g2  = (const float*)d_in[19];
    const float* be2 = (const float*)d_in[20];
    float* out = (float*)d_out;

    float *t0f, *t1f, *t2f, *big;
    __half *t0h, *t2h, *wh;
    cudaGetSymbolAddress((void**)&t0f, g_t0f);
    cudaGetSymbolAddress((void**)&t0h, g_t0h);
    cudaGetSymbolAddress((void**)&t1f, g_t1f);
    cudaGetSymbolAddress((void**)&t2f, g_t2f);
    cudaGetSymbolAddress((void**)&t2h, g_t2h);
    cudaGetSymbolAddress((void**)&big, g_big);
    cudaGetSymbolAddress((void**)&wh, g_wh);

    float* qkvf = big;                                       // MM x 1152 fp32
    __half* ao  = (__half*)(big + (size_t)MM * 1152);        // MM x 384 fp16
    __half* mlph = (__half*)big;                             // MM x 1536 fp16 (MLP phase)
    float* t3f = t0f;                                        // t0 dead after attention

    // weight pool offsets (elements): per axial i, [Wqkv_t 1152x384], then Wo_t, W1m_t, W2m_t
    const size_t QKV_OFF = 442368;               // 1152*384
    const size_t O_BASE  = 3 * QKV_OFF;          // 1327104
    const size_t O_SZ    = 147456;               // 384*384
    const size_t W1_OFF  = O_BASE + 3 * O_SZ;    // 1769472
    const size_t W2_OFF  = W1_OFF + 589824;      // 2359296

    cudaFuncSetAttribute(mma_gemm<EPI_STORE>,      cudaFuncAttributeMaxDynamicSharedMemorySize, GEMM_SMEM);
    cudaFuncSetAttribute(mma_gemm<EPI_ACCUM_BIAS>, cudaFuncAttributeMaxDynamicSharedMemorySize, GEMM_SMEM);
    cudaFuncSetAttribute(mma_gemm<EPI_GELU_BIAS>,  cudaFuncAttributeMaxDynamicSharedMemorySize, GEMM_SMEM);
    cudaFuncSetAttribute(mma_gemm<EPI_BIAS_RESID>, cudaFuncAttributeMaxDynamicSharedMemorySize, GEMM_SMEM);

    dim3 tb(32, 8);
    // weight transpose + fp16 convert
    for (int i = 0; i < 3; i++) {
        wconv_kernel<<<dim3(384 / 32, 384 / 32), tb>>>(Wq[i],  wh + i * QKV_OFF,          384, 384);
        wconv_kernel<<<dim3(768 / 32, 384 / 32), tb>>>(Wkv[i], wh + i * QKV_OFF + 147456, 384, 768);
        wconv_kernel<<<dim3(384 / 32, 384 / 32), tb>>>(Wo[i],  wh + O_BASE + i * O_SZ,    384, 384);
    }
    wconv_kernel<<<dim3(1536 / 32, 384 / 32), tb>>>(W1m, wh + W1_OFF, 384, 1536);
    wconv_kernel<<<dim3(384 / 32, 1536 / 32), tb>>>(W2m, wh + W2_OFF, 1536, 384);

    transpose_in_kernel<<<dim3(SS / 32, CC / 32, BB), tb>>>(x, t0f, t0h);

    for (int i = 0; i < 3; i++) {
        // fused qkv projection: N=1152 (Wq_t rows 0-383, Wkv_t rows 384-1151)
        mma_gemm<EPI_STORE><<<dim3(9, MM / 128), 256, GEMM_SMEM>>>(
            t0h, wh + i * QKV_OFF, qkvf, nullptr, nullptr, nullptr, 384, 1152);
        if (i == 0)      attn3_kernel<<<BB * 256, 128>>>(qkvf, ao);
        else if (i == 1) attn16_kernel<16, 1><<<dim3(BB * 48, 12), 128>>>(qkvf, ao);
        else             attn16_kernel<1, 2><<<dim3(BB * 48, 12), 128>>>(qkvf, ao);
        if (i == 0)
            mma_gemm<EPI_BIAS_RESID><<<dim3(3, MM / 128), 256, GEMM_SMEM>>>(
                ao, wh + O_BASE, t1f, nullptr, bo[0], t0f, 384, 384);
        else
            mma_gemm<EPI_ACCUM_BIAS><<<dim3(3, MM / 128), 256, GEMM_SMEM>>>(
                ao, wh + O_BASE + i * O_SZ, t1f, nullptr, bo[i], nullptr, 384, 384);
    }

    layernorm_kernel<true><<<MM / 8, 256>>>(t1f, t2f, t2h, g1, be1);
    mma_gemm<EPI_GELU_BIAS><<<dim3(12, MM / 128), 256, GEMM_SMEM>>>(
        t2h, wh + W1_OFF, nullptr, mlph, b1m, nullptr, 384, 1536);
    mma_gemm<EPI_BIAS_RESID><<<dim3(3, MM / 128), 256, GEMM_SMEM>>>(
        mlph, wh + W2_OFF, t3f, nullptr, b2m, t2f, 1536, 384);
    layernorm_kernel<false><<<MM / 8, 256>>>(t3f, t1f, nullptr, g2, be2);

    transpose_out_kernel<<<dim3(SS / 32, CC / 32, BB), tb>>>(t1f, out);
}